// round 3
// baseline (speedup 1.0000x reference)
#include <cuda_runtime.h>

// Problem constants (B=256, S=1024, H=128)
#define B_TOT 256
#define SEQ   1024
#define HID   128
#define G3    (3 * HID)      // 384
#define NTHR  384            // one thread per W_hh row
#define BPC   2              // batches per CTA
#define NCTA  (B_TOT / BPC)  // 128 CTAs -> 1 wave on 148 SMs

// Packed 2xfp32 FMA (Blackwell f32x2 path; ptxas will not auto-fuse from C++)
__device__ __forceinline__ unsigned long long ffma2(unsigned long long a,
                                                    unsigned long long b,
                                                    unsigned long long c) {
    unsigned long long d;
    asm("fma.rn.f32x2 %0, %1, %2, %3;" : "=l"(d) : "l"(a), "l"(b), "l"(c));
    return d;
}

__device__ __forceinline__ float2 unpack_f32x2(unsigned long long v) {
    float2 f;
    asm("mov.b64 {%0, %1}, %2;" : "=f"(f.x), "=f"(f.y) : "l"(v));
    return f;
}

__device__ __forceinline__ float sigmoid_acc(float x) {
    // 1/(1+e^-x); __expf rel err ~1e-6, far inside the 1e-3 budget
    return 1.0f / (1.0f + __expf(-x));
}

__device__ __forceinline__ float tanh_acc(float x) {
    // accurate tanh from __expf (avoid tanh.approx's 2^-11 error)
    float ax = fabsf(x);
    float e  = __expf(-2.0f * ax);
    float r  = (1.0f - e) / (1.0f + e);
    return copysignf(r, x);
}

__global__ void __launch_bounds__(NTHR, 1)
gru_fused_kernel(const float* __restrict__ x,     // [B, S]
                 const float* __restrict__ w_ih,  // [3H]
                 const float* __restrict__ w_hh,  // [3H, H]
                 const float* __restrict__ b_ih,  // [3H]
                 const float* __restrict__ b_hh,  // [3H]
                 const float* __restrict__ w_fc,  // [H]
                 const float* __restrict__ b_fc,  // [1]
                 float* __restrict__ out)         // [B]
{
    __shared__ __align__(16) float x_sh[BPC * SEQ];   // 8 KB
    __shared__ __align__(16) float h_sh[BPC][HID];    // hidden states
    __shared__ float gh_sh[BPC][G3];                  // gate pre-activations
    __shared__ float in_sh[BPC][HID];                 // i_n (input-side of n gate)
    __shared__ float red_sh[BPC * HID];               // fc reduction scratch

    const int t   = threadIdx.x;        // 0..383: row of W_hh
    const int b0  = blockIdx.x * BPC;   // first batch of this CTA

    // ---- Persistent per-thread state: one W_hh row in registers (64 x f32x2) ----
    unsigned long long w2[HID / 2];
    {
        const ulonglong2* wr = reinterpret_cast<const ulonglong2*>(w_hh + t * HID);
        #pragma unroll
        for (int i = 0; i < HID / 4; i++) {   // 32 x 16B loads
            ulonglong2 v = wr[i];
            w2[2 * i]     = v.x;
            w2[2 * i + 1] = v.y;
        }
    }
    const float wih_t = w_ih[t];
    const float bih_t = b_ih[t];
    const float bhh_t = b_hh[t];

    // ---- Stage x for both batches (contiguous rows b0, b0+1) ----
    for (int i = t; i < BPC * SEQ; i += NTHR)
        x_sh[i] = x[b0 * SEQ + i];
    if (t < BPC * HID)
        h_sh[t >> 7][t & 127] = 0.0f;
    __syncthreads();

    const int gate = t >> 7;     // 0=r, 1=z, 2=n
    const int j    = t & 127;    // hidden unit

    for (int s = 0; s < SEQ; s++) {
        // ---- gh[t] = dot(W_hh[t,:], h)  for both batches, packed f32x2 ----
        unsigned long long a0 = 0ull, a1 = 0ull, a2 = 0ull, a3 = 0ull;
        const ulonglong2* h0 = reinterpret_cast<const ulonglong2*>(h_sh[0]);
        const ulonglong2* h1 = reinterpret_cast<const ulonglong2*>(h_sh[1]);
        #pragma unroll
        for (int i = 0; i < HID / 4; i++) {
            ulonglong2 v0 = h0[i];   // broadcast LDS.128 (conflict-free)
            ulonglong2 v1 = h1[i];
            a0 = ffma2(w2[2 * i],     v0.x, a0);
            a1 = ffma2(w2[2 * i + 1], v0.y, a1);
            a2 = ffma2(w2[2 * i],     v1.x, a2);
            a3 = ffma2(w2[2 * i + 1], v1.y, a3);
        }
        float2 f0 = unpack_f32x2(a0), f1 = unpack_f32x2(a1);
        float2 f2 = unpack_f32x2(a2), f3 = unpack_f32x2(a3);
        float d0 = (f0.x + f0.y) + (f1.x + f1.y);
        float d1 = (f2.x + f2.y) + (f3.x + f3.y);

        float gi0 = fmaf(x_sh[s],       wih_t, bih_t);
        float gi1 = fmaf(x_sh[SEQ + s], wih_t, bih_t);
        float gh0 = d0 + bhh_t;
        float gh1 = d1 + bhh_t;

        if (gate < 2) {
            // r / z gates: store i + gh combined
            gh_sh[0][t] = gh0 + gi0;
            gh_sh[1][t] = gh1 + gi1;
        } else {
            // n gate: keep gh and i separate (n = tanh(i_n + r*gh_n))
            gh_sh[0][t] = gh0;
            gh_sh[1][t] = gh1;
            in_sh[0][j] = gi0;
            in_sh[1][j] = gi1;
        }
        __syncthreads();

        // ---- gate nonlinearities + state update (256 threads: 128 per batch) ----
        if (t < BPC * HID) {
            const int bb = t >> 7;
            const int jj = t & 127;
            float r = sigmoid_acc(gh_sh[bb][jj]);
            float z = sigmoid_acc(gh_sh[bb][HID + jj]);
            float n = tanh_acc(in_sh[bb][jj] + r * gh_sh[bb][2 * HID + jj]);
            float hprev = h_sh[bb][jj];
            h_sh[bb][jj] = (1.0f - z) * n + z * hprev;
        }
        __syncthreads();
    }

    // ---- fused fc1: out[b] = relu(hT) . w_fc + b_fc ----
    if (t < BPC * HID) {
        const int bb = t >> 7;
        const int jj = t & 127;
        red_sh[t] = fmaxf(h_sh[bb][jj], 0.0f) * w_fc[jj];
    }
    __syncthreads();
    if (t < BPC) {
        float acc = b_fc[0];
        #pragma unroll 8
        for (int k = 0; k < HID; k++)
            acc += red_sh[t * HID + k];
        out[b0 + t] = acc;
    }
}

extern "C" void kernel_launch(void* const* d_in, const int* in_sizes, int n_in,
                              void* d_out, int out_size) {
    const float* x    = (const float*)d_in[0];
    const float* w_ih = (const float*)d_in[1];
    const float* w_hh = (const float*)d_in[2];
    const float* b_ih = (const float*)d_in[3];
    const float* b_hh = (const float*)d_in[4];
    const float* w_fc = (const float*)d_in[5];
    const float* b_fc = (const float*)d_in[6];
    float* out = (float*)d_out;

    gru_fused_kernel<<<NCTA, NTHR>>>(x, w_ih, w_hh, b_ih, b_hh, w_fc, b_fc, out);
}